// round 15
// baseline (speedup 1.0000x reference)
#include <cuda_runtime.h>
#include <cuda_bf16.h>
#include <math.h>
#include <stdint.h>

// ---------------- problem constants ----------------
#define BB     64
#define HH     56
#define WW_    56
#define CC     192
#define LL     (HH*WW_)            // 3136
#define MROWS  (BB*LL)             // 200704
#define NHEADS 6
#define HD     32
#define NT     64
#define NWIN   49
#define BWIN   (BB*NWIN)           // 3136
#define HID    768
#define QKVN   576
#define SCALE_ 0.17677669529663687f

// GEMM tiling (bf16 m16n8k16), 2-stage pipeline (known-good R8)
#define BM 256
#define BN 64
#define BK 32
#define LDA2 20     // uint32 row stride (16 data + 4 pad) -> conflict-free
#define LDB2 20
#define SMEM_BYTES ((2*BM*LDA2 + 2*BN*LDB2) * 4)   // 51200

// ---------------- scratch ----------------
__device__ __nv_bfloat16 g_xw  [(size_t)MROWS * CC];
__device__ __nv_bfloat16 g_qkv [(size_t)MROWS * QKVN];
__device__ __nv_bfloat16 g_attn[(size_t)MROWS * CC];
__device__ __nv_bfloat16 g_xn2 [(size_t)MROWS * CC];
__device__ __nv_bfloat16 g_h1  [(size_t)MROWS * HID];
__device__ __nv_bfloat16 g_wb  [110592 + 36864 + 147456 + 147456]; // transposed [N][K] bf16

#define WOFF_QKV  0
#define WOFF_PROJ 110592
#define WOFF_FC1  147456
#define WOFF_FC2  294912

__device__ __forceinline__ uint32_t smem_u32(const void* p) {
    uint32_t a;
    asm("{.reg .u64 t; cvta.to.shared.u64 t, %1; cvt.u32.u64 %0, t;}" : "=r"(a) : "l"(p));
    return a;
}
__device__ __forceinline__ void cp_async16(uint32_t dst, const void* src) {
    asm volatile("cp.async.cg.shared.global [%0], [%1], 16;\n" :: "r"(dst), "l"(src));
}
__device__ __forceinline__ void ldsm_x4(uint32_t* r, uint32_t addr) {
    asm volatile("ldmatrix.sync.aligned.m8n8.x4.shared.b16 {%0,%1,%2,%3}, [%4];"
                 : "=r"(r[0]), "=r"(r[1]), "=r"(r[2]), "=r"(r[3]) : "r"(addr));
}
__device__ __forceinline__ void mma_bf16(float* c, const uint32_t* a, const uint32_t* b) {
    asm volatile(
        "mma.sync.aligned.m16n8k16.row.col.f32.bf16.bf16.f32 "
        "{%0,%1,%2,%3}, {%4,%5,%6,%7}, {%8,%9}, {%0,%1,%2,%3};\n"
        : "+f"(c[0]), "+f"(c[1]), "+f"(c[2]), "+f"(c[3])
        : "r"(a[0]), "r"(a[1]), "r"(a[2]), "r"(a[3]), "r"(b[0]), "r"(b[1]));
}
__device__ __forceinline__ uint32_t packbf(float x, float y) {
    __nv_bfloat162 p = __floats2bfloat162_rn(x, y);
    return *(uint32_t*)&p;
}

__device__ __forceinline__ int win_to_global(int wrow) {
    int b_  = wrow >> 6;
    int n   = wrow & 63;
    int b   = b_ / NWIN;
    int wi  = b_ - b * NWIN;
    int hp  = (wi / 7) * 8 + (n >> 3);
    int wp  = (wi % 7) * 8 + (n & 7);
    int h = hp + 4; if (h >= HH)  h -= HH;
    int w = wp + 4; if (w >= WW_) w -= WW_;
    return b * LL + h * WW_ + w;
}

// ---------------- weight prep: bf16 + transpose to [N][K] ----------------
__global__ void prep_w_kernel(const float* __restrict__ qkv_w,
                              const float* __restrict__ proj_w,
                              const float* __restrict__ fc1_w,
                              const float* __restrict__ fc2_w)
{
    int i = blockIdx.x * 256 + threadIdx.x;
    if (i < 192 * 576) {
        int k = i / 576, n = i % 576;
        g_wb[WOFF_QKV + n * 192 + k] = __float2bfloat16_rn(qkv_w[i]);
    }
    if (i < 192 * 192) {
        int k = i / 192, n = i % 192;
        g_wb[WOFF_PROJ + n * 192 + k] = __float2bfloat16_rn(proj_w[i]);
    }
    if (i < 192 * 768) {
        int k = i / 768, n = i % 768;
        g_wb[WOFF_FC1 + n * 192 + k] = __float2bfloat16_rn(fc1_w[i]);
    }
    if (i < 768 * 192) {
        int k = i / 192, n = i % 192;
        g_wb[WOFF_FC2 + n * 768 + k] = __float2bfloat16_rn(fc2_w[i]);
    }
}

// ---------------- LayerNorm -> bf16 ----------------
template<bool MAP>
__global__ void ln_kernel(const float* __restrict__ x,
                          const float* __restrict__ w,
                          const float* __restrict__ b,
                          __nv_bfloat16* __restrict__ out)
{
    int row = blockIdx.x;
    int tid = threadIdx.x;
    int g = MAP ? win_to_global(row) : row;
    float v = x[(size_t)g * CC + tid];

    __shared__ float sh[12];
    float s = v, s2 = v * v;
    #pragma unroll
    for (int o = 16; o; o >>= 1) {
        s  += __shfl_xor_sync(0xffffffffu, s,  o);
        s2 += __shfl_xor_sync(0xffffffffu, s2, o);
    }
    int wp = tid >> 5;
    if ((tid & 31) == 0) { sh[wp] = s; sh[6 + wp] = s2; }
    __syncthreads();
    float ts = 0.f, ts2 = 0.f;
    #pragma unroll
    for (int i = 0; i < 6; i++) { ts += sh[i]; ts2 += sh[6 + i]; }
    const float inv = 1.f / 192.f;
    float mu  = ts * inv;
    float var = ts2 * inv - mu * mu;
    float rs  = rsqrtf(var + 1e-5f);
    out[(size_t)row * CC + tid] = __float2bfloat16_rn((v - mu) * rs * w[tid] + b[tid]);
}

// ---------------- bf16 tensor-core GEMM with ldmatrix (R8, 2-stage) ----------------
template<int EPI, typename OutT>
__global__ void __launch_bounds__(256)
gemm_bf(const __nv_bfloat16* __restrict__ A, const __nv_bfloat16* __restrict__ Wt,
        const float* __restrict__ bias, const float* __restrict__ res,
        OutT* __restrict__ Cout, int M, int N, int K)
{
    extern __shared__ uint32_t smem[];
    uint32_t* As = smem;                     // [2][BM][LDA2]
    uint32_t* Bs = smem + 2 * BM * LDA2;     // [2][BN][LDB2]

    const int tid  = threadIdx.x;
    const int wid  = tid >> 5, lane = tid & 31;
    const int bm   = blockIdx.y * BM, bn = blockIdx.x * BN;
    const int warp_m = (wid >> 1) * 64;
    const int warp_n = (wid & 1) * 32;
    const int lr = lane >> 2, lc = lane & 3;

    float acc[4][4][4];
    #pragma unroll
    for (int f = 0; f < 4; f++)
        #pragma unroll
        for (int g = 0; g < 4; g++)
            #pragma unroll
            for (int r = 0; r < 4; r++) acc[f][g][r] = 0.f;

    auto load_tiles = [&](int k0, int stage) {
        uint32_t* as = As + stage * (BM * LDA2);
        uint32_t* bs = Bs + stage * (BN * LDB2);
        #pragma unroll
        for (int i = 0; i < 4; i++) {
            int idx = tid + i * 256;
            int r = idx >> 2, c = idx & 3;
            cp_async16(smem_u32(&as[r * LDA2 + c * 4]),
                       A + (size_t)(bm + r) * K + k0 + c * 8);
        }
        {
            int r = tid >> 2, c = tid & 3;
            cp_async16(smem_u32(&bs[r * LDB2 + c * 4]),
                       Wt + (size_t)(bn + r) * K + k0 + c * 8);
        }
        asm volatile("cp.async.commit_group;\n");
    };

    const int g8 = lane >> 3;
    const int a_row = (lane & 7) + ((g8 & 1) << 3);
    const int a_k   = (g8 >> 1) << 2;
    const int b_row = (lane & 7) + ((lane & 16) ? 8 : 0);
    const int b_k   = (lane & 8) ? 4 : 0;

    uint32_t aBase[2], bBase[2];
    #pragma unroll
    for (int st = 0; st < 2; st++) {
        aBase[st] = smem_u32(As + st * (BM * LDA2) + (warp_m + a_row) * LDA2 + a_k);
        bBase[st] = smem_u32(Bs + st * (BN * LDB2) + (warp_n + b_row) * LDB2 + b_k);
    }

    load_tiles(0, 0);
    asm volatile("cp.async.wait_group 0;\n");
    __syncthreads();

    const int KT = K >> 5;
    for (int kt = 0; kt < KT; kt++) {
        int stage = kt & 1;
        if (kt + 1 < KT) load_tiles((kt + 1) << 5, stage ^ 1);

        #pragma unroll
        for (int ks = 0; ks < 2; ks++) {
            uint32_t a[4][4];
            #pragma unroll
            for (int f = 0; f < 4; f++)
                ldsm_x4(a[f], aBase[stage] + (uint32_t)((f * 16 * LDA2 + ks * 8) * 4));
            uint32_t b[4][2];
            #pragma unroll
            for (int gp = 0; gp < 2; gp++) {
                uint32_t r[4];
                ldsm_x4(r, bBase[stage] + (uint32_t)((gp * 16 * LDB2 + ks * 8) * 4));
                b[gp * 2 + 0][0] = r[0]; b[gp * 2 + 0][1] = r[1];
                b[gp * 2 + 1][0] = r[2]; b[gp * 2 + 1][1] = r[3];
            }
            #pragma unroll
            for (int f = 0; f < 4; f++)
                #pragma unroll
                for (int g = 0; g < 4; g++)
                    mma_bf16(acc[f][g], a[f], b[g]);
        }
        asm volatile("cp.async.wait_group 0;\n");
        __syncthreads();
    }

    // epilogue
    #pragma unroll
    for (int f = 0; f < 4; f++) {
        #pragma unroll
        for (int i = 0; i < 2; i++) {
            int m  = bm + warp_m + f * 16 + lr + i * 8;
            int gm = (EPI == 2) ? win_to_global(m) : m;
            #pragma unroll
            for (int g = 0; g < 4; g++) {
                int n = bn + warp_n + g * 8 + lc * 2;
                float v0 = acc[f][g][i * 2 + 0] + bias[n];
                float v1 = acc[f][g][i * 2 + 1] + bias[n + 1];
                if (EPI == 1) {
                    v0 = 0.5f * v0 * (1.f + erff(v0 * 0.70710678118654752f));
                    v1 = 0.5f * v1 * (1.f + erff(v1 * 0.70710678118654752f));
                }
                if (EPI == 0 || EPI == 1) {
                    *(__nv_bfloat162*)((__nv_bfloat16*)Cout + (size_t)m * N + n) =
                        __floats2bfloat162_rn(v0, v1);
                } else {
                    const float* rp = res + (size_t)((EPI == 2) ? gm : m) * N + n;
                    float2 r2 = *(const float2*)rp;
                    v0 += r2.x; v1 += r2.y;
                    *(float2*)((float*)Cout + (size_t)gm * N + n) = make_float2(v0, v1);
                }
            }
        }
    }
}

// ---------------- bf16 tensor-core windowed attention, 4 warps x 16 rows ----------------
// block = (window, head), 128 threads = 4 warps; warp w owns query rows [16w, 16w+16).
// Halved per-warp register state vs the 2-warp version -> ~1.5x occupancy.
__global__ void __launch_bounds__(128)
attn_mma_kernel(const __nv_bfloat16* __restrict__ qkv, const float* __restrict__ rpb,
                __nv_bfloat16* __restrict__ out)
{
    const int b_   = blockIdx.x;
    const int h    = blockIdx.y;
    const int tid  = threadIdx.x;
    const int warp = tid >> 5, lane = tid & 31;

    __shared__ uint32_t Ks[NT * 20];     // [key][dim] bf16, row stride 20 words
    __shared__ uint32_t Vt[HD * 36];     // [dim][key] bf16, row stride 36 words
    __shared__ float    bias_s[225];
    __shared__ int      reg_s[NT];

    const __nv_bfloat16* base = qkv + (size_t)b_ * NT * QKVN;

    // K: raw 16B copies into [key][dim] layout
    for (int i = tid; i < 256; i += 128) {
        int r = i >> 2, c = i & 3;
        uint4 v = *(const uint4*)(base + r * QKVN + 192 + h * HD + c * 8);
        *(uint4*)&Ks[r * 20 + c * 4] = v;
    }
    // V: transpose to [dim][key] (scalar bf16; coalesced gmem reads)
    {
        __nv_bfloat16* vt = (__nv_bfloat16*)Vt;
        for (int i = tid; i < NT * HD; i += 128) {
            int k = i >> 5, d = i & 31;
            vt[d * 72 + k] = base[k * QKVN + 384 + h * HD + d];
        }
    }
    for (int i = tid; i < 225; i += 128) bias_s[i] = rpb[i * NHEADS + h];
    if (tid < NT) {
        int wi = b_ % NWIN;
        int r = tid >> 3, c = tid & 7;
        int gh = (wi / 7) * 8 + r;
        int gw = (wi % 7) * 8 + c;
        reg_s[tid] = ((gh < 48) ? 0 : (gh < 52 ? 1 : 2)) * 3
                   + ((gw < 48) ? 0 : (gw < 52 ? 1 : 2));
    }
    __syncthreads();

    const int m0 = warp * 16;
    const int lr = lane >> 2, lc = lane & 3;

    // Q A-frags straight from gmem (raw bf16 pairs; scale applied post-mma)
    uint32_t qa[2][4];
    #pragma unroll
    for (int ks = 0; ks < 2; ks++) {
        const __nv_bfloat16* qp = base + (size_t)(m0 + lr) * QKVN
                                + h * HD + ks * 16 + 2 * lc;
        qa[ks][0] = *(const uint32_t*)(qp);
        qa[ks][1] = *(const uint32_t*)(qp + 8 * QKVN);
        qa[ks][2] = *(const uint32_t*)(qp + 8);
        qa[ks][3] = *(const uint32_t*)(qp + 8 * QKVN + 8);
    }

    // S = Q @ K^T : M=16, N=64, K=32 (2 k16 steps)
    float sacc[8][4];
    #pragma unroll
    for (int nf = 0; nf < 8; nf++)
        #pragma unroll
        for (int e = 0; e < 4; e++) sacc[nf][e] = 0.f;

    #pragma unroll
    for (int ks = 0; ks < 2; ks++) {
        #pragma unroll
        for (int nf = 0; nf < 8; nf++) {
            uint32_t kb[2];
            int w0 = (nf * 8 + lr) * 20 + ks * 8 + lc;
            kb[0] = Ks[w0];
            kb[1] = Ks[w0 + 4];
            mma_bf16(sacc[nf], qa[ks], kb);
        }
    }

    // scale + bias + mask + softmax (row owned by a 4-lane group)
    #pragma unroll
    for (int half = 0; half < 2; half++) {
        int row = m0 + lr + half * 8;
        int r1 = row >> 3, c1 = row & 7, myreg = reg_s[row];
        float mx = -1e30f;
        #pragma unroll
        for (int nf = 0; nf < 8; nf++)
            #pragma unroll
            for (int j = 0; j < 2; j++) {
                int col = nf * 8 + lc * 2 + j;
                float v = sacc[nf][half * 2 + j] * SCALE_
                        + bias_s[(r1 - (col >> 3) + 7) * 15 + (c1 - (col & 7) + 7)];
                if (reg_s[col] != myreg) v -= 100.f;
                sacc[nf][half * 2 + j] = v;
                mx = fmaxf(mx, v);
            }
        mx = fmaxf(mx, __shfl_xor_sync(0xffffffffu, mx, 1));
        mx = fmaxf(mx, __shfl_xor_sync(0xffffffffu, mx, 2));
        float sum = 0.f;
        #pragma unroll
        for (int nf = 0; nf < 8; nf++)
            #pragma unroll
            for (int j = 0; j < 2; j++) {
                float e = __expf(sacc[nf][half * 2 + j] - mx);
                sacc[nf][half * 2 + j] = e;
                sum += e;
            }
        sum += __shfl_xor_sync(0xffffffffu, sum, 1);
        sum += __shfl_xor_sync(0xffffffffu, sum, 2);
        float rinv = 1.f / sum;
        #pragma unroll
        for (int nf = 0; nf < 8; nf++)
            #pragma unroll
            for (int j = 0; j < 2; j++)
                sacc[nf][half * 2 + j] *= rinv;
    }

    // O = P @ V : M=16, N=32, K=64 (4 k16 steps).
    // P C-frags (two adjacent n8 tiles) pack in-lane into one m16k16 A-frag.
    float pacc[4][4];
    #pragma unroll
    for (int nf = 0; nf < 4; nf++)
        #pragma unroll
        for (int e = 0; e < 4; e++) pacc[nf][e] = 0.f;

    #pragma unroll
    for (int kc = 0; kc < 4; kc++) {
        uint32_t pa[4];
        pa[0] = packbf(sacc[2 * kc][0],     sacc[2 * kc][1]);
        pa[1] = packbf(sacc[2 * kc][2],     sacc[2 * kc][3]);
        pa[2] = packbf(sacc[2 * kc + 1][0], sacc[2 * kc + 1][1]);
        pa[3] = packbf(sacc[2 * kc + 1][2], sacc[2 * kc + 1][3]);
        #pragma unroll
        for (int nf = 0; nf < 4; nf++) {
            uint32_t vb[2];
            int w0 = (nf * 8 + lr) * 36 + kc * 8 + lc;
            vb[0] = Vt[w0];
            vb[1] = Vt[w0 + 4];
            mma_bf16(pacc[nf], pa, vb);
        }
    }

    // store bf16 (feeds proj GEMM)
    {
        int row = m0 + lr;
        #pragma unroll
        for (int nf = 0; nf < 4; nf++) {
            int col = h * HD + nf * 8 + lc * 2;
            __nv_bfloat16* o = out + (size_t)(b_ * NT + row) * CC + col;
            *(__nv_bfloat162*)o = __floats2bfloat162_rn(pacc[nf][0], pacc[nf][1]);
            *(__nv_bfloat162*)(o + 8 * CC) = __floats2bfloat162_rn(pacc[nf][2], pacc[nf][3]);
        }
    }
}

// ---------------- launch ----------------
extern "C" void kernel_launch(void* const* d_in, const int* in_sizes, int n_in,
                              void* d_out, int out_size)
{
    const float* x      = (const float*)d_in[0];
    const float* ln1_w  = (const float*)d_in[1];
    const float* ln1_b  = (const float*)d_in[2];
    const float* qkv_w  = (const float*)d_in[3];
    const float* qkv_b  = (const float*)d_in[4];
    const float* proj_w = (const float*)d_in[5];
    const float* proj_b = (const float*)d_in[6];
    const float* rpb    = (const float*)d_in[7];
    const float* ln2_w  = (const float*)d_in[8];
    const float* ln2_b  = (const float*)d_in[9];
    const float* fc1_w  = (const float*)d_in[10];
    const float* fc1_b  = (const float*)d_in[11];
    const float* fc2_w  = (const float*)d_in[12];
    const float* fc2_b  = (const float*)d_in[13];
    float* out = (float*)d_out;

    __nv_bfloat16 *xw, *qkv, *attn, *xn2, *h1, *wb;
    cudaGetSymbolAddress((void**)&xw,   g_xw);
    cudaGetSymbolAddress((void**)&qkv,  g_qkv);
    cudaGetSymbolAddress((void**)&attn, g_attn);
    cudaGetSymbolAddress((void**)&xn2,  g_xn2);
    cudaGetSymbolAddress((void**)&h1,   g_h1);
    cudaGetSymbolAddress((void**)&wb,   g_wb);

    cudaFuncSetAttribute(gemm_bf<0, __nv_bfloat16>,
                         cudaFuncAttributeMaxDynamicSharedMemorySize, SMEM_BYTES);
    cudaFuncSetAttribute(gemm_bf<1, __nv_bfloat16>,
                         cudaFuncAttributeMaxDynamicSharedMemorySize, SMEM_BYTES);
    cudaFuncSetAttribute(gemm_bf<2, float>,
                         cudaFuncAttributeMaxDynamicSharedMemorySize, SMEM_BYTES);
    cudaFuncSetAttribute(gemm_bf<3, float>,
                         cudaFuncAttributeMaxDynamicSharedMemorySize, SMEM_BYTES);

    prep_w_kernel<<<(147456 + 255) / 256, 256>>>(qkv_w, proj_w, fc1_w, fc2_w);
    ln_kernel<true><<<MROWS, CC>>>(x, ln1_w, ln1_b, xw);
    gemm_bf<0, __nv_bfloat16><<<dim3(QKVN / BN, MROWS / BM), 256, SMEM_BYTES>>>(
        xw, wb + WOFF_QKV, qkv_b, nullptr, qkv, MROWS, QKVN, CC);
    attn_mma_kernel<<<dim3(BWIN, NHEADS), 128>>>(qkv, rpb, attn);
    gemm_bf<2, float><<<dim3(CC / BN, MROWS / BM), 256, SMEM_BYTES>>>(
        attn, wb + WOFF_PROJ, proj_b, x, out, MROWS, CC, CC);
    ln_kernel<false><<<MROWS, CC>>>(out, ln2_w, ln2_b, xn2);
    gemm_bf<1, __nv_bfloat16><<<dim3(HID / BN, MROWS / BM), 256, SMEM_BYTES>>>(
        xn2, wb + WOFF_FC1, fc1_b, nullptr, h1, MROWS, HID, CC);
    gemm_bf<3, float><<<dim3(CC / BN, MROWS / BM), 256, SMEM_BYTES>>>(
        h1, wb + WOFF_FC2, fc2_b, out, out, MROWS, CC, HID);
}